// round 14
// baseline (speedup 1.0000x reference)
#include <cuda_runtime.h>
#include <cstdint>

// EmbeddingDropout: out[b,s,:] = weight[x[b,s],:] * rowmask(x[b,s])
// rowmask = jax.random.bernoulli(jax.random.key(42), 0.9, (V,1)) / 0.9 under
// jax_threefry_partitionable=True:
//   (o0,o1) = threefry2x32(key=(0,42), counter=(0, row)); bits = o0 ^ o1
//   u = bitcast((bits>>9)|0x3f800000) - 1.0 ;  keep iff u < 0.9
// x indices are int32.
// Persistent grid-stride kernel: one wave of CTAs, each looping over token
// batches; next batch's Threefry hashes are computed (double-buffered smem)
// while the current batch's row loads are in flight.

#define D 1024            // embedding dim (floats)
#define THREADS 256       // one float4 per thread per token row
#define TPC 8             // tokens per batch
#define CTAS_PER_SM 5
#define NUM_SMS 148

__device__ __forceinline__ uint32_t rotl32(uint32_t x, uint32_t d) {
    return (x << d) | (x >> (32u - d));
}

// Threefry-2x32 with key (0, 42); returns both output lanes.
__device__ __forceinline__ void threefry2x32_42(uint32_t c0, uint32_t c1,
                                                uint32_t& o0, uint32_t& o1) {
    const uint32_t ks0 = 0u;
    const uint32_t ks1 = 42u;
    const uint32_t ks2 = 0u ^ 42u ^ 0x1BD11BDAu;
    uint32_t ks[3] = {ks0, ks1, ks2};

    uint32_t x0 = c0 + ks0;
    uint32_t x1 = c1 + ks1;

    const uint32_t rotA[4] = {13u, 15u, 26u, 6u};
    const uint32_t rotB[4] = {17u, 29u, 16u, 24u};

    #pragma unroll
    for (int g = 0; g < 5; ++g) {
        const uint32_t* rot = (g & 1) ? rotB : rotA;
        #pragma unroll
        for (int r = 0; r < 4; ++r) {
            x0 += x1;
            x1 = rotl32(x1, rot[r]);
            x1 ^= x0;
        }
        x0 += ks[(g + 1) % 3];
        x1 += ks[(g + 2) % 3] + (uint32_t)(g + 1);
    }
    o0 = x0;
    o1 = x1;
}

__device__ __forceinline__ float row_scale(int v) {
    uint32_t o0, o1;
    threefry2x32_42(0u, (uint32_t)v, o0, o1);
    uint32_t bits = o0 ^ o1;   // partitionable 32-bit path: XOR fold
    float u = __uint_as_float((bits >> 9) | 0x3f800000u) - 1.0f;
    return (u < 0.9f) ? (1.0f / 0.9f) : 0.0f;
}

__global__ void __launch_bounds__(THREADS, CTAS_PER_SM)
EmbeddingDropout_29875792511459_kernel(const int* __restrict__ x,
                                       const float* __restrict__ weight,
                                       float* __restrict__ out,
                                       int vocab, int n_tokens,
                                       int n_batches) {
    __shared__ int   s_idx[2][TPC];
    __shared__ float s_scl[2][TPC];

    const int t = threadIdx.x;
    const int stride = gridDim.x;

    // Prologue: hash this CTA's first batch into buffer 0.
    int b0 = blockIdx.x;
    if (t < TPC && b0 < n_batches) {
        int tok = min(b0 * TPC + t, n_tokens - 1);
        int v = x[tok];
        v = min(max(v, 0), vocab - 1);
        s_idx[0][t] = v;
        s_scl[0][t] = row_scale(v);
    }
    __syncthreads();

    int buf = 0;
    for (int b = b0; b < n_batches; b += stride, buf ^= 1) {
        const int base = b * TPC;

        // Snapshot current batch's indices/scales into registers.
        int   idx[TPC];
        float scl[TPC];
        #pragma unroll
        for (int k = 0; k < TPC; ++k) {
            idx[k] = s_idx[buf][k];
            scl[k] = s_scl[buf][k];
        }

        // Front-batch the independent row loads (dropped rows predicated off).
        float4 val[TPC];
        #pragma unroll
        for (int k = 0; k < TPC; ++k) {
            if (scl[k] != 0.0f) {
                const float4* src =
                    reinterpret_cast<const float4*>(weight + (size_t)idx[k] * D);
                val[k] = __ldg(&src[t]);
            } else {
                val[k] = make_float4(0.0f, 0.0f, 0.0f, 0.0f);
            }
        }

        // Overlap: hash the NEXT batch while loads are in flight.
        const int bn = b + stride;
        if (t < TPC && bn < n_batches) {
            int tok = min(bn * TPC + t, n_tokens - 1);
            int v = x[tok];
            v = min(max(v, 0), vocab - 1);
            s_idx[buf ^ 1][t] = v;
            s_scl[buf ^ 1][t] = row_scale(v);
        }

        // Scale + streaming store (keeps weight rows resident in L2).
        #pragma unroll
        for (int k = 0; k < TPC; ++k) {
            const int tok = base + k;
            if (tok < n_tokens) {
                const float s = scl[k];
                float4 r = val[k];
                r.x *= s; r.y *= s; r.z *= s; r.w *= s;
                float4* dst = reinterpret_cast<float4*>(out + (size_t)tok * D);
                __stcs(&dst[t], r);
            }
        }

        __syncthreads();   // next-buffer hashes visible; safe to reuse buf
    }
}

extern "C" void kernel_launch(void* const* d_in, const int* in_sizes, int n_in,
                              void* d_out, int out_size) {
    const int* x        = (const int*)d_in[0];          // int32 [8,2048]
    const float* weight = (const float*)d_in[1];        // fp32 [50257,1024]
    float* out          = (float*)d_out;                // fp32 [8,2048,1024]

    const int n_tokens  = in_sizes[0];                  // 16384
    const int vocab     = in_sizes[1] / D;              // 50257
    const int n_batches = (n_tokens + TPC - 1) / TPC;   // 2048

    int grid = NUM_SMS * CTAS_PER_SM;                   // one persistent wave
    if (grid > n_batches) grid = n_batches;

    EmbeddingDropout_29875792511459_kernel<<<grid, THREADS>>>(
        x, weight, out, vocab, n_tokens, n_batches);
}

// round 16
// speedup vs baseline: 1.2424x; 1.2424x over previous
#include <cuda_runtime.h>
#include <cstdint>

// EmbeddingDropout: out[b,s,:] = weight[x[b,s],:] * rowmask(x[b,s])
// rowmask = jax.random.bernoulli(jax.random.key(42), 0.9, (V,1)) / 0.9 under
// jax_threefry_partitionable=True:
//   (o0,o1) = threefry2x32(key=(0,42), counter=(0, row)); bits = o0 ^ o1
//   u = bitcast((bits>>9)|0x3f800000) - 1.0 ;  keep iff u < 0.9
// x indices are int32.
//
// Warp-autonomous variant: each warp's lanes 0..7 load+hash the CTA's 8
// token indices themselves (coalesced 32B LDG, L1-hit after warp 0), then
// idx/scale are broadcast via shfl. No smem, no __syncthreads -> each warp
// issues its row loads as soon as its own hash chain retires.

#define D 1024            // embedding dim (floats)
#define THREADS 256       // one float4 per thread per token row
#define TPC 8             // tokens per CTA

__device__ __forceinline__ uint32_t rotl32(uint32_t x, uint32_t d) {
    return (x << d) | (x >> (32u - d));
}

// Threefry-2x32 with key (0, 42); returns both output lanes.
__device__ __forceinline__ void threefry2x32_42(uint32_t c0, uint32_t c1,
                                                uint32_t& o0, uint32_t& o1) {
    const uint32_t ks0 = 0u;
    const uint32_t ks1 = 42u;
    const uint32_t ks2 = 0u ^ 42u ^ 0x1BD11BDAu;
    uint32_t ks[3] = {ks0, ks1, ks2};

    uint32_t x0 = c0 + ks0;
    uint32_t x1 = c1 + ks1;

    const uint32_t rotA[4] = {13u, 15u, 26u, 6u};
    const uint32_t rotB[4] = {17u, 29u, 16u, 24u};

    #pragma unroll
    for (int g = 0; g < 5; ++g) {
        const uint32_t* rot = (g & 1) ? rotB : rotA;
        #pragma unroll
        for (int r = 0; r < 4; ++r) {
            x0 += x1;
            x1 = rotl32(x1, rot[r]);
            x1 ^= x0;
        }
        x0 += ks[(g + 1) % 3];
        x1 += ks[(g + 2) % 3] + (uint32_t)(g + 1);
    }
    o0 = x0;
    o1 = x1;
}

__device__ __forceinline__ float row_scale(int v) {
    uint32_t o0, o1;
    threefry2x32_42(0u, (uint32_t)v, o0, o1);
    uint32_t bits = o0 ^ o1;   // partitionable 32-bit path: XOR fold
    float u = __uint_as_float((bits >> 9) | 0x3f800000u) - 1.0f;
    return (u < 0.9f) ? (1.0f / 0.9f) : 0.0f;
}

__global__ void __launch_bounds__(THREADS)
EmbeddingDropout_29875792511459_kernel(const int* __restrict__ x,
                                       const float* __restrict__ weight,
                                       float* __restrict__ out,
                                       int vocab) {
    const int base = blockIdx.x * TPC;   // grid is exact: 16384/8 = 2048
    const int t    = threadIdx.x;
    const int lane = t & 31;

    // Lanes 0..7 of EVERY warp load + hash the CTA's 8 indices (no smem,
    // no barrier; ~8x redundant hashing is noise on the ALU pipe).
    int   my_v = 0;
    float my_s = 0.0f;
    if (lane < TPC) {
        int v = x[base + lane];
        v = min(max(v, 0), vocab - 1);
        my_v = v;
        my_s = row_scale(v);
    }

    // Broadcast idx/scale from lanes 0..7, front-batch the row loads.
    int   idx[TPC];
    float scl[TPC];
    #pragma unroll
    for (int k = 0; k < TPC; ++k) {
        idx[k] = __shfl_sync(0xffffffffu, my_v, k);
        scl[k] = __shfl_sync(0xffffffffu, my_s, k);
    }

    float4 val[TPC];
    #pragma unroll
    for (int k = 0; k < TPC; ++k) {
        if (scl[k] != 0.0f) {
            const float4* src =
                reinterpret_cast<const float4*>(weight + (size_t)idx[k] * D);
            val[k] = __ldg(&src[t]);
        } else {
            val[k] = make_float4(0.0f, 0.0f, 0.0f, 0.0f);
        }
    }

    #pragma unroll
    for (int k = 0; k < TPC; ++k) {
        const float s = scl[k];
        float4 r = val[k];
        r.x *= s; r.y *= s; r.z *= s; r.w *= s;
        float4* dst =
            reinterpret_cast<float4*>(out + (size_t)(base + k) * D);
        __stcs(&dst[t], r);   // streaming store: keep weight rows in L2
    }
}

extern "C" void kernel_launch(void* const* d_in, const int* in_sizes, int n_in,
                              void* d_out, int out_size) {
    const int* x        = (const int*)d_in[0];          // int32 [8,2048]
    const float* weight = (const float*)d_in[1];        // fp32 [50257,1024]
    float* out          = (float*)d_out;                // fp32 [8,2048,1024]

    const int n_tokens = in_sizes[0];                   // 16384
    const int vocab    = in_sizes[1] / D;               // 50257
    const int n_blocks = (n_tokens + TPC - 1) / TPC;    // 2048 (exact)

    EmbeddingDropout_29875792511459_kernel<<<n_blocks, THREADS>>>(
        x, weight, out, vocab);
}